// round 12
// baseline (speedup 1.0000x reference)
#include <cuda_runtime.h>
#include <cuda_fp16.h>
#include <cstdint>

#define BB 4
#define TT 4096
#define DD 2048
#define MM (BB*TT)   // 16384
#define NC 64
#define LC (TT/NC)

// ---------------- scratch (device globals) ----------------------------------
__device__ __half g_mixh[3][(size_t)MM*DD];   // kmix, vmix, rmix (fp16)
__device__ __half g_Wh  [4][(size_t)DD*DD];   // Wk, Wv, Wr, Wo (fp16)
__device__ __half g_kvh [2][(size_t)MM*DD];   // k, v (fp16)
__device__ __half g_rh  [(size_t)MM*DD];      // r (fp16)
__device__ __half g_wkvrh[(size_t)MM*DD];     // (a/b)*r (fp16)
__device__ float g_P [(size_t)BB*NC*DD];
__device__ float g_A [(size_t)BB*NC*DD];
__device__ float g_Bc[(size_t)BB*NC*DD];
__device__ float g_iA[(size_t)BB*NC*DD];
__device__ float g_iB[(size_t)BB*NC*DD];

// ---------------- helpers -----------------------------------------------------
__device__ __forceinline__ void cp16(uint32_t dst, const void* src) {
    asm volatile("cp.async.cg.shared.global [%0], [%1], 16;" :: "r"(dst), "l"(src));
}
__device__ __forceinline__ void ldsm4(uint32_t& r0, uint32_t& r1, uint32_t& r2,
                                      uint32_t& r3, uint32_t addr) {
    asm volatile("ldmatrix.sync.aligned.m8n8.x4.shared.b16 {%0,%1,%2,%3}, [%4];"
                 : "=r"(r0), "=r"(r1), "=r"(r2), "=r"(r3) : "r"(addr));
}

// ---------------- weight convert (fp32 -> fp16) -------------------------------
__global__ void wconv_kernel(const float* __restrict__ w0, const float* __restrict__ w1,
                             const float* __restrict__ w2, const float* __restrict__ w3,
                             __half* __restrict__ out) {
    int i = blockIdx.x * blockDim.x + threadIdx.x;
    if (i >= DD * DD / 4) return;
    const float* src = (blockIdx.y == 0) ? w0 : (blockIdx.y == 1) ? w1 :
                       (blockIdx.y == 2) ? w2 : w3;
    float4 v = ((const float4*)src)[i];
    __half2 h01 = __floats2half2_rn(v.x, v.y);
    __half2 h23 = __floats2half2_rn(v.z, v.w);
    __half2* dst = (__half2*)(out + (size_t)blockIdx.y * DD * DD) + i * 2;
    dst[0] = h01; dst[1] = h23;
}

// ---------------- mix_kv: time-shift + lerp for k,v -> fp16 -------------------
__global__ void mix_kv_kernel(const float* __restrict__ x,
                              const float* __restrict__ tmk,
                              const float* __restrict__ tmv,
                              __half* __restrict__ km,
                              __half* __restrict__ vm) {
    int i4 = blockIdx.x * blockDim.x + threadIdx.x;
    if (i4 >= MM * DD / 4) return;
    size_t i = (size_t)i4 * 4;
    int m = (int)(i / DD);
    int d = (int)(i % DD);
    int t = m % TT;
    float4 xv = *(const float4*)(x + i);
    float4 xs = (t > 0) ? *(const float4*)(x + i - DD) : make_float4(0.f, 0.f, 0.f, 0.f);
    float4 mk = *(const float4*)(tmk + d);
    float4 mv = *(const float4*)(tmv + d);

    ((__half2*)(km + i))[0] = __floats2half2_rn(xv.x * mk.x + xs.x * (1.f - mk.x),
                                                xv.y * mk.y + xs.y * (1.f - mk.y));
    ((__half2*)(km + i))[1] = __floats2half2_rn(xv.z * mk.z + xs.z * (1.f - mk.z),
                                                xv.w * mk.w + xs.w * (1.f - mk.w));
    ((__half2*)(vm + i))[0] = __floats2half2_rn(xv.x * mv.x + xs.x * (1.f - mv.x),
                                                xv.y * mv.y + xs.y * (1.f - mv.y));
    ((__half2*)(vm + i))[1] = __floats2half2_rn(xv.z * mv.z + xs.z * (1.f - mv.z),
                                                xv.w * mv.w + xs.w * (1.f - mv.w));
}

// ---------------- mix_r: time-shift + lerp + silu -> fp16 ----------------------
__global__ void mix_r_kernel(const float* __restrict__ x,
                             const float* __restrict__ tmr,
                             __half* __restrict__ rm) {
    int i4 = blockIdx.x * blockDim.x + threadIdx.x;
    if (i4 >= MM * DD / 4) return;
    size_t i = (size_t)i4 * 4;
    int m = (int)(i / DD);
    int d = (int)(i % DD);
    int t = m % TT;
    float4 xv = *(const float4*)(x + i);
    float4 xs = (t > 0) ? *(const float4*)(x + i - DD) : make_float4(0.f, 0.f, 0.f, 0.f);
    float4 mr = *(const float4*)(tmr + d);

    float s0, s1, s2, s3;
    s0 = xv.x * mr.x + xs.x * (1.f - mr.x); s0 = s0 / (1.f + __expf(-s0));
    s1 = xv.y * mr.y + xs.y * (1.f - mr.y); s1 = s1 / (1.f + __expf(-s1));
    s2 = xv.z * mr.z + xs.z * (1.f - mr.z); s2 = s2 / (1.f + __expf(-s2));
    s3 = xv.w * mr.w + xs.w * (1.f - mr.w); s3 = s3 / (1.f + __expf(-s3));
    ((__half2*)(rm + i))[0] = __floats2half2_rn(s0, s1);
    ((__half2*)(rm + i))[1] = __floats2half2_rn(s2, s3);
}

// ---------------- fp16 GEMM: 128 threads, 2x2 warps of 64x64, 2 CTAs/SM ---------
constexpr int BM = 128, BN = 128, BKH = 64, STAGES = 3;
constexpr int A_STAGE_B = BM * 128;
constexpr int B_STAGE_B = BN * 128;
constexpr int STAGE_B   = A_STAGE_B + B_STAGE_B;  // 32768
constexpr int GSMEM     = STAGES * STAGE_B;       // 98304

__global__ __launch_bounds__(128, 2)
void gemm_fp16(const __half* __restrict__ Abase, const __half* __restrict__ Wbase,
               const float* __restrict__ b0p, const float* __restrict__ b1p,
               float* __restrict__ Cbase, __half* __restrict__ Chbase) {
    extern __shared__ char smem[];
    uint32_t sb = (uint32_t)__cvta_generic_to_shared(smem);
    const int K = DD, N = DD;

    int z = blockIdx.z;
    const __half* A = Abase + (size_t)z * MM * DD;
    const __half* W = Wbase + (size_t)z * DD * DD;
    const float* bias = (z == 0) ? b0p : b1p;

    int tid  = threadIdx.x;
    int m0   = blockIdx.y * BM;
    int n0   = blockIdx.x * BN;
    int warp = tid >> 5, lane = tid & 31;
    int wm = warp >> 1, wn = warp & 1;
    int g  = lane >> 2, tg = lane & 3;

    float acc[4][8][4];
#pragma unroll
    for (int a = 0; a < 4; a++)
#pragma unroll
        for (int b = 0; b < 8; b++)
#pragma unroll
            for (int c = 0; c < 4; c++) acc[a][b][c] = 0.f;

    auto load_stage = [&](int s, int ko) {
        uint32_t base = sb + s * STAGE_B;
#pragma unroll
        for (int i = 0; i < 8; i++) {
            int c  = tid + i * 128;
            int r  = c >> 3;
            int gp = c & 7;
            int pg = gp ^ (r & 7);
            cp16(base + (uint32_t)(r * 128 + pg * 16),
                 A + (size_t)(m0 + r) * K + ko + gp * 8);
        }
#pragma unroll
        for (int i = 0; i < 8; i++) {
            int c  = tid + i * 128;
            int r  = c >> 3;
            int gp = c & 7;
            int pg = gp ^ (r & 7);
            cp16(base + (uint32_t)(A_STAGE_B + r * 128 + pg * 16),
                 W + (size_t)(n0 + r) * K + ko + gp * 8);
        }
        asm volatile("cp.async.commit_group;");
    };

    load_stage(0, 0);
    load_stage(1, BKH);

    int a_row16 = lane & 15;
    int a_khalf = lane >> 4;
    int b_row   = ((lane >> 4) << 3) + (lane & 7);
    int b_khalf = (lane >> 3) & 1;

    const int KT = K / BKH;   // 32
    for (int kt = 0; kt < KT; kt++) {
        if (kt < KT - 1) asm volatile("cp.async.wait_group 1;");
        else             asm volatile("cp.async.wait_group 0;");
        __syncthreads();
        if (kt + 2 < KT) load_stage((kt + 2) % 3, (kt + 2) * BKH);

        uint32_t sa  = sb + (kt % 3) * STAGE_B;
        uint32_t sbm = sa + A_STAGE_B;
#pragma unroll
        for (int ks = 0; ks < 4; ks++) {
            int kg = ks * 2;
            uint32_t af[4][4], bf[8][2];
#pragma unroll
            for (int mt = 0; mt < 4; mt++) {
                int mr = wm * 64 + mt * 16 + a_row16;
                int gp = (kg + a_khalf) ^ (mr & 7);
                ldsm4(af[mt][0], af[mt][1], af[mt][2], af[mt][3],
                      sa + (uint32_t)(mr * 128 + gp * 16));
            }
#pragma unroll
            for (int p = 0; p < 4; p++) {
                int nr = wn * 64 + p * 16 + b_row;
                int gp = (kg + b_khalf) ^ (nr & 7);
                ldsm4(bf[2 * p][0], bf[2 * p][1], bf[2 * p + 1][0], bf[2 * p + 1][1],
                      sbm + (uint32_t)(nr * 128 + gp * 16));
            }
#pragma unroll
            for (int mt = 0; mt < 4; mt++)
#pragma unroll
                for (int nt = 0; nt < 8; nt++) {
                    asm volatile(
                        "mma.sync.aligned.m16n8k16.row.col.f32.f16.f16.f32 "
                        "{%0,%1,%2,%3}, {%4,%5,%6,%7}, {%8,%9}, {%0,%1,%2,%3};"
                        : "+f"(acc[mt][nt][0]), "+f"(acc[mt][nt][1]),
                          "+f"(acc[mt][nt][2]), "+f"(acc[mt][nt][3])
                        : "r"(af[mt][0]), "r"(af[mt][1]), "r"(af[mt][2]), "r"(af[mt][3]),
                          "r"(bf[nt][0]), "r"(bf[nt][1]));
                }
        }
    }

    if (Chbase != nullptr) {
        __half* Ch = Chbase + (size_t)z * MM * DD;
#pragma unroll
        for (int mt = 0; mt < 4; mt++) {
#pragma unroll
            for (int nt = 0; nt < 8; nt++) {
                int m = m0 + wm * 64 + mt * 16 + g;
                int n = n0 + wn * 64 + nt * 8 + tg * 2;
                float b0 = bias[n], b1 = bias[n + 1];
                *(__half2*)(Ch + (size_t)m * N + n) =
                    __floats2half2_rn(acc[mt][nt][0] + b0, acc[mt][nt][1] + b1);
                *(__half2*)(Ch + (size_t)(m + 8) * N + n) =
                    __floats2half2_rn(acc[mt][nt][2] + b0, acc[mt][nt][3] + b1);
            }
        }
    } else {
        float* C = Cbase;
#pragma unroll
        for (int mt = 0; mt < 4; mt++) {
#pragma unroll
            for (int nt = 0; nt < 8; nt++) {
                int m = m0 + wm * 64 + mt * 16 + g;
                int n = n0 + wn * 64 + nt * 8 + tg * 2;
                float b0 = bias[n], b1 = bias[n + 1];
                float2 v0 = make_float2(acc[mt][nt][0] + b0, acc[mt][nt][1] + b1);
                float2 v1 = make_float2(acc[mt][nt][2] + b0, acc[mt][nt][3] + b1);
                *(float2*)(C + (size_t)m * N + n)       = v0;
                *(float2*)(C + (size_t)(m + 8) * N + n) = v1;
            }
        }
    }
}

// ---------------- chunked WKV scan (fp16 inputs, fp32 math) ---------------------
__global__ void wkv_pass1(const __half* __restrict__ k, const __half* __restrict__ v,
                          const float* __restrict__ u, const float* __restrict__ w,
                          float* __restrict__ P, float* __restrict__ A,
                          float* __restrict__ Bc) {
    int idx = blockIdx.x * blockDim.x + threadIdx.x;
    if (idx >= BB * NC * DD) return;
    int d = idx % DD;
    int rest = idx / DD;
    int c = rest % NC;
    int b = rest / NC;
    float uu = u[d], ww = w[d];
    size_t base = ((size_t)b * TT + (size_t)c * LC) * DD + d;
    float Pp = 1.f, Aa = 0.f, Bb = 0.f;
#pragma unroll 4
    for (int t = 0; t < LC; t++) {
        size_t off = base + (size_t)t * DD;
        float kt = __half2float(k[off]), vt = __half2float(v[off]);
        float mx = fmaxf(uu + kt, ww);
        float e1 = __expf(-ww - mx);
        float e2 = __expf(uu + kt - mx);
        Aa = fmaf(e1, Aa, e2 * vt);
        Bb = fmaf(e1, Bb, e2);
        Pp *= e1;
    }
    size_t o = ((size_t)b * NC + c) * DD + d;
    P[o] = Pp; A[o] = Aa; Bc[o] = Bb;
}

__global__ void wkv_combine(const float* __restrict__ P, const float* __restrict__ A,
                            const float* __restrict__ Bc,
                            float* __restrict__ iA, float* __restrict__ iB) {
    int idx = blockIdx.x * blockDim.x + threadIdx.x;
    if (idx >= BB * DD) return;
    int d = idx % DD, b = idx / DD;
    float a = 0.f, bd = 0.f;
    for (int c = 0; c < NC; c++) {
        size_t o = ((size_t)b * NC + c) * DD + d;
        iA[o] = a; iB[o] = bd;
        a  = fmaf(P[o], a,  A[o]);
        bd = fmaf(P[o], bd, Bc[o]);
    }
}

// pass3: replay chunks from true init state; write (a/b)*r (fp16)
__global__ void wkv_pass3(const __half* __restrict__ k, const __half* __restrict__ v,
                          const __half* __restrict__ r,
                          const float* __restrict__ u, const float* __restrict__ w,
                          const float* __restrict__ iA, const float* __restrict__ iB,
                          __half* __restrict__ out) {
    int idx = blockIdx.x * blockDim.x + threadIdx.x;
    if (idx >= BB * NC * DD) return;
    int d = idx % DD;
    int rest = idx / DD;
    int c = rest % NC;
    int b = rest / NC;
    float uu = u[d], ww = w[d];
    size_t base = ((size_t)b * TT + (size_t)c * LC) * DD + d;
    size_t o = ((size_t)b * NC + c) * DD + d;
    float a = iA[o], bd = iB[o];
#pragma unroll 4
    for (int t = 0; t < LC; t++) {
        size_t off = base + (size_t)t * DD;
        float kt = __half2float(k[off]), vt = __half2float(v[off]);
        float mx = fmaxf(uu + kt, ww);
        float e1 = __expf(-ww - mx);
        float e2 = __expf(uu + kt - mx);
        a  = fmaf(e1, a,  e2 * vt);
        bd = fmaf(e1, bd, e2);
        out[off] = __float2half_rn((a / bd) * __half2float(r[off]));
    }
}

// ---------------- launch ---------------------------------------------------------
extern "C" void kernel_launch(void* const* d_in, const int* in_sizes, int n_in,
                              void* d_out, int out_size) {
    (void)in_sizes; (void)n_in; (void)out_size;
    const float* x   = (const float*)d_in[0];
    const float* Wk  = (const float*)d_in[1];
    const float* bk  = (const float*)d_in[2];
    const float* Wv  = (const float*)d_in[3];
    const float* bv  = (const float*)d_in[4];
    const float* Wr  = (const float*)d_in[5];
    const float* br  = (const float*)d_in[6];
    const float* Wo  = (const float*)d_in[7];
    const float* bo  = (const float*)d_in[8];
    const float* tmk = (const float*)d_in[9];
    const float* tmv = (const float*)d_in[10];
    const float* tmr = (const float*)d_in[11];
    const float* u   = (const float*)d_in[12];
    const float* w   = (const float*)d_in[13];
    float* out = (float*)d_out;

    __half *mixh, *Wh, *kvh, *rh, *wkvrh;
    float *P, *A, *Bc, *iA, *iB;
    cudaGetSymbolAddress((void**)&mixh,  g_mixh);
    cudaGetSymbolAddress((void**)&Wh,    g_Wh);
    cudaGetSymbolAddress((void**)&kvh,   g_kvh);
    cudaGetSymbolAddress((void**)&rh,    g_rh);
    cudaGetSymbolAddress((void**)&wkvrh, g_wkvrh);
    cudaGetSymbolAddress((void**)&P,     g_P);
    cudaGetSymbolAddress((void**)&A,     g_A);
    cudaGetSymbolAddress((void**)&Bc,    g_Bc);
    cudaGetSymbolAddress((void**)&iA,    g_iA);
    cudaGetSymbolAddress((void**)&iB,    g_iB);
    __half* kmix = mixh;
    __half* vmix = mixh + (size_t)MM * DD;
    __half* rmix = mixh + 2 * (size_t)MM * DD;
    __half* kh = kvh;
    __half* vh = kvh + (size_t)MM * DD;
    __half* Wr16 = Wh + 2 * (size_t)DD * DD;
    __half* Wo16 = Wh + 3 * (size_t)DD * DD;

    static cudaStream_t s1 = nullptr;
    static cudaEvent_t ev0, evW, evMR, evKV, evB;
    if (s1 == nullptr) {
        cudaStreamCreateWithFlags(&s1, cudaStreamNonBlocking);
        cudaEventCreateWithFlags(&ev0,  cudaEventDisableTiming);
        cudaEventCreateWithFlags(&evW,  cudaEventDisableTiming);
        cudaEventCreateWithFlags(&evMR, cudaEventDisableTiming);
        cudaEventCreateWithFlags(&evKV, cudaEventDisableTiming);
        cudaEventCreateWithFlags(&evB,  cudaEventDisableTiming);
    }

    cudaFuncSetAttribute(gemm_fp16, cudaFuncAttributeMaxDynamicSharedMemorySize, GSMEM);

    // fork: wconv (then mix_r) on s1; mix_kv on main
    cudaEventRecord(ev0, 0);
    cudaStreamWaitEvent(s1, ev0, 0);
    dim3 wcGrid((DD * DD / 4 + 255) / 256, 4);
    wconv_kernel<<<wcGrid, 256, 0, s1>>>(Wk, Wv, Wr, Wo, Wh);
    cudaEventRecord(evW, s1);    // weights ready (kv GEMM only needs this)
    int mixBlocks = (MM * DD / 4 + 255) / 256;
    mix_r_kernel<<<mixBlocks, 256, 0, s1>>>(x, tmr, rmix);
    cudaEventRecord(evMR, s1);   // rmix ready

    mix_kv_kernel<<<mixBlocks, 256>>>(x, tmk, tmv, kmix, vmix);
    cudaStreamWaitEvent(0, evW, 0);

    // kv GEMMs (z=0,1) -> fp16, full launch (wave-friendly)
    dim3 gkv(DD / BN, MM / BM, 2);   // (16, 128, 2)
    gemm_fp16<<<gkv, 128, GSMEM>>>(mixh, Wh, bk, bv, nullptr, kvh);
    cudaEventRecord(evKV, 0);

    // r GEMM (full) on s1, after kv completes; needs rmix (s1-ordered)
    cudaStreamWaitEvent(s1, evKV, 0);
    dim3 gr(DD / BN, MM / BM, 1);    // (16, 128, 1)
    gemm_fp16<<<gr, 128, GSMEM, s1>>>(rmix, Wr16, br, br, nullptr, rh);
    cudaEventRecord(evB, s1);

    // scan chain on main, overlapping the r GEMM tail
    int scanThreads = BB * NC * DD;
    wkv_pass1<<<scanThreads / 256, 256>>>(kh, vh, u, w, P, A, Bc);
    wkv_combine<<<(BB * DD + 255) / 256, 256>>>(P, A, Bc, iA, iB);

    cudaStreamWaitEvent(0, evB, 0);
    wkv_pass3<<<scanThreads / 256, 256>>>(kh, vh, rh, u, w, iA, iB, wkvrh);

    // out GEMM (full, fp32 out)
    gemm_fp16<<<gr, 128, GSMEM>>>(wkvrh, Wo16, bo, bo, out, nullptr);
}

// round 13
// speedup vs baseline: 1.0544x; 1.0544x over previous
#include <cuda_runtime.h>
#include <cuda_fp16.h>
#include <cstdint>

#define BB 4
#define TT 4096
#define DD 2048
#define MM (BB*TT)   // 16384
#define NC 64
#define LC (TT/NC)

// ---------------- scratch (device globals) ----------------------------------
__device__ __half g_mixh[3][(size_t)MM*DD];   // kmix, vmix, rmix (fp16)
__device__ __half g_Wh  [4][(size_t)DD*DD];   // Wk, Wv, Wr, Wo (fp16)
__device__ __half g_kvh [2][(size_t)MM*DD];   // k, v (fp16)
__device__ __half g_rh  [(size_t)MM*DD];      // r (fp16)
__device__ __half g_wkvrh[(size_t)MM*DD];     // (a/b)*r (fp16)
__device__ float g_P [(size_t)BB*NC*DD];
__device__ float g_A [(size_t)BB*NC*DD];
__device__ float g_Bc[(size_t)BB*NC*DD];
__device__ float g_iA[(size_t)BB*NC*DD];
__device__ float g_iB[(size_t)BB*NC*DD];

// ---------------- helpers -----------------------------------------------------
__device__ __forceinline__ void cp16(uint32_t dst, const void* src) {
    asm volatile("cp.async.cg.shared.global [%0], [%1], 16;" :: "r"(dst), "l"(src));
}
__device__ __forceinline__ void ldsm4(uint32_t& r0, uint32_t& r1, uint32_t& r2,
                                      uint32_t& r3, uint32_t addr) {
    asm volatile("ldmatrix.sync.aligned.m8n8.x4.shared.b16 {%0,%1,%2,%3}, [%4];"
                 : "=r"(r0), "=r"(r1), "=r"(r2), "=r"(r3) : "r"(addr));
}

// ---------------- weight convert (fp32 -> fp16) -------------------------------
__global__ void wconv_kernel(const float* __restrict__ w0, const float* __restrict__ w1,
                             const float* __restrict__ w2, const float* __restrict__ w3,
                             __half* __restrict__ out) {
    int i = blockIdx.x * blockDim.x + threadIdx.x;
    if (i >= DD * DD / 4) return;
    const float* src = (blockIdx.y == 0) ? w0 : (blockIdx.y == 1) ? w1 :
                       (blockIdx.y == 2) ? w2 : w3;
    float4 v = ((const float4*)src)[i];
    __half2 h01 = __floats2half2_rn(v.x, v.y);
    __half2 h23 = __floats2half2_rn(v.z, v.w);
    __half2* dst = (__half2*)(out + (size_t)blockIdx.y * DD * DD) + i * 2;
    dst[0] = h01; dst[1] = h23;
}

// ---------------- mix: time-shift + lerp (+silu for r) -> fp16 ----------------
__global__ void mix_kernel(const float* __restrict__ x,
                           const float* __restrict__ tmk,
                           const float* __restrict__ tmv,
                           const float* __restrict__ tmr,
                           __half* __restrict__ km,
                           __half* __restrict__ vm,
                           __half* __restrict__ rm) {
    int i4 = blockIdx.x * blockDim.x + threadIdx.x;
    if (i4 >= MM * DD / 4) return;
    size_t i = (size_t)i4 * 4;
    int m = (int)(i / DD);
    int d = (int)(i % DD);
    int t = m % TT;
    float4 xv = *(const float4*)(x + i);
    float4 xs = (t > 0) ? *(const float4*)(x + i - DD) : make_float4(0.f, 0.f, 0.f, 0.f);
    float4 mk = *(const float4*)(tmk + d);
    float4 mv = *(const float4*)(tmv + d);
    float4 mr = *(const float4*)(tmr + d);

    __half2 h01, h23;
    h01 = __floats2half2_rn(xv.x * mk.x + xs.x * (1.f - mk.x),
                            xv.y * mk.y + xs.y * (1.f - mk.y));
    h23 = __floats2half2_rn(xv.z * mk.z + xs.z * (1.f - mk.z),
                            xv.w * mk.w + xs.w * (1.f - mk.w));
    ((__half2*)(km + i))[0] = h01; ((__half2*)(km + i))[1] = h23;

    h01 = __floats2half2_rn(xv.x * mv.x + xs.x * (1.f - mv.x),
                            xv.y * mv.y + xs.y * (1.f - mv.y));
    h23 = __floats2half2_rn(xv.z * mv.z + xs.z * (1.f - mv.z),
                            xv.w * mv.w + xs.w * (1.f - mv.w));
    ((__half2*)(vm + i))[0] = h01; ((__half2*)(vm + i))[1] = h23;

    float s0, s1, s2, s3;
    s0 = xv.x * mr.x + xs.x * (1.f - mr.x); s0 = s0 / (1.f + __expf(-s0));
    s1 = xv.y * mr.y + xs.y * (1.f - mr.y); s1 = s1 / (1.f + __expf(-s1));
    s2 = xv.z * mr.z + xs.z * (1.f - mr.z); s2 = s2 / (1.f + __expf(-s2));
    s3 = xv.w * mr.w + xs.w * (1.f - mr.w); s3 = s3 / (1.f + __expf(-s3));
    ((__half2*)(rm + i))[0] = __floats2half2_rn(s0, s1);
    ((__half2*)(rm + i))[1] = __floats2half2_rn(s2, s3);
}

// ---------------- fp16 GEMM: 128 threads, 2x2 warps of 64x64, 2 CTAs/SM ---------
constexpr int BM = 128, BN = 128, BKH = 64, STAGES = 3;
constexpr int A_STAGE_B = BM * 128;
constexpr int B_STAGE_B = BN * 128;
constexpr int STAGE_B   = A_STAGE_B + B_STAGE_B;  // 32768
constexpr int GSMEM     = STAGES * STAGE_B;       // 98304

__global__ __launch_bounds__(128, 2)
void gemm_fp16(const __half* __restrict__ Abase, const __half* __restrict__ Wbase,
               const float* __restrict__ b0p, const float* __restrict__ b1p,
               float* __restrict__ Cbase, __half* __restrict__ Chbase) {
    extern __shared__ char smem[];
    uint32_t sb = (uint32_t)__cvta_generic_to_shared(smem);
    const int K = DD, N = DD;

    int z = blockIdx.z;
    const __half* A = Abase + (size_t)z * MM * DD;
    const __half* W = Wbase + (size_t)z * DD * DD;
    const float* bias = (z == 0) ? b0p : b1p;

    int tid  = threadIdx.x;
    int m0   = blockIdx.y * BM;
    int n0   = blockIdx.x * BN;
    int warp = tid >> 5, lane = tid & 31;
    int wm = warp >> 1, wn = warp & 1;
    int g  = lane >> 2, tg = lane & 3;

    float acc[4][8][4];
#pragma unroll
    for (int a = 0; a < 4; a++)
#pragma unroll
        for (int b = 0; b < 8; b++)
#pragma unroll
            for (int c = 0; c < 4; c++) acc[a][b][c] = 0.f;

    auto load_stage = [&](int s, int ko) {
        uint32_t base = sb + s * STAGE_B;
#pragma unroll
        for (int i = 0; i < 8; i++) {
            int c  = tid + i * 128;
            int r  = c >> 3;
            int gp = c & 7;
            int pg = gp ^ (r & 7);
            cp16(base + (uint32_t)(r * 128 + pg * 16),
                 A + (size_t)(m0 + r) * K + ko + gp * 8);
        }
#pragma unroll
        for (int i = 0; i < 8; i++) {
            int c  = tid + i * 128;
            int r  = c >> 3;
            int gp = c & 7;
            int pg = gp ^ (r & 7);
            cp16(base + (uint32_t)(A_STAGE_B + r * 128 + pg * 16),
                 W + (size_t)(n0 + r) * K + ko + gp * 8);
        }
        asm volatile("cp.async.commit_group;");
    };

    load_stage(0, 0);
    load_stage(1, BKH);

    int a_row16 = lane & 15;
    int a_khalf = lane >> 4;
    int b_row   = ((lane >> 4) << 3) + (lane & 7);
    int b_khalf = (lane >> 3) & 1;

    const int KT = K / BKH;   // 32
    for (int kt = 0; kt < KT; kt++) {
        if (kt < KT - 1) asm volatile("cp.async.wait_group 1;");
        else             asm volatile("cp.async.wait_group 0;");
        __syncthreads();
        if (kt + 2 < KT) load_stage((kt + 2) % 3, (kt + 2) * BKH);

        uint32_t sa  = sb + (kt % 3) * STAGE_B;
        uint32_t sbm = sa + A_STAGE_B;
#pragma unroll
        for (int ks = 0; ks < 4; ks++) {
            int kg = ks * 2;
            uint32_t af[4][4], bf[8][2];
#pragma unroll
            for (int mt = 0; mt < 4; mt++) {
                int mr = wm * 64 + mt * 16 + a_row16;
                int gp = (kg + a_khalf) ^ (mr & 7);
                ldsm4(af[mt][0], af[mt][1], af[mt][2], af[mt][3],
                      sa + (uint32_t)(mr * 128 + gp * 16));
            }
#pragma unroll
            for (int p = 0; p < 4; p++) {
                int nr = wn * 64 + p * 16 + b_row;
                int gp = (kg + b_khalf) ^ (nr & 7);
                ldsm4(bf[2 * p][0], bf[2 * p][1], bf[2 * p + 1][0], bf[2 * p + 1][1],
                      sbm + (uint32_t)(nr * 128 + gp * 16));
            }
#pragma unroll
            for (int mt = 0; mt < 4; mt++)
#pragma unroll
                for (int nt = 0; nt < 8; nt++) {
                    asm volatile(
                        "mma.sync.aligned.m16n8k16.row.col.f32.f16.f16.f32 "
                        "{%0,%1,%2,%3}, {%4,%5,%6,%7}, {%8,%9}, {%0,%1,%2,%3};"
                        : "+f"(acc[mt][nt][0]), "+f"(acc[mt][nt][1]),
                          "+f"(acc[mt][nt][2]), "+f"(acc[mt][nt][3])
                        : "r"(af[mt][0]), "r"(af[mt][1]), "r"(af[mt][2]), "r"(af[mt][3]),
                          "r"(bf[nt][0]), "r"(bf[nt][1]));
                }
        }
    }

    if (Chbase != nullptr) {
        __half* Ch = Chbase + (size_t)z * MM * DD;
#pragma unroll
        for (int mt = 0; mt < 4; mt++) {
#pragma unroll
            for (int nt = 0; nt < 8; nt++) {
                int m = m0 + wm * 64 + mt * 16 + g;
                int n = n0 + wn * 64 + nt * 8 + tg * 2;
                float b0 = bias[n], b1 = bias[n + 1];
                *(__half2*)(Ch + (size_t)m * N + n) =
                    __floats2half2_rn(acc[mt][nt][0] + b0, acc[mt][nt][1] + b1);
                *(__half2*)(Ch + (size_t)(m + 8) * N + n) =
                    __floats2half2_rn(acc[mt][nt][2] + b0, acc[mt][nt][3] + b1);
            }
        }
    } else {
        float* C = Cbase;
#pragma unroll
        for (int mt = 0; mt < 4; mt++) {
#pragma unroll
            for (int nt = 0; nt < 8; nt++) {
                int m = m0 + wm * 64 + mt * 16 + g;
                int n = n0 + wn * 64 + nt * 8 + tg * 2;
                float b0 = bias[n], b1 = bias[n + 1];
                float2 v0 = make_float2(acc[mt][nt][0] + b0, acc[mt][nt][1] + b1);
                float2 v1 = make_float2(acc[mt][nt][2] + b0, acc[mt][nt][3] + b1);
                *(float2*)(C + (size_t)m * N + n)       = v0;
                *(float2*)(C + (size_t)(m + 8) * N + n) = v1;
            }
        }
    }
}

// ---------------- chunked WKV scan: 2 channels/thread (__half2 / float2) --------
__global__ void wkv_pass1(const __half* __restrict__ k, const __half* __restrict__ v,
                          const float* __restrict__ u, const float* __restrict__ w,
                          float* __restrict__ P, float* __restrict__ A,
                          float* __restrict__ Bc) {
    int idx = blockIdx.x * blockDim.x + threadIdx.x;   // over BB*NC*DD/2
    if (idx >= BB * NC * DD / 2) return;
    int d2 = idx % (DD / 2);
    int rest = idx / (DD / 2);
    int c = rest % NC;
    int b = rest / NC;
    int d = d2 * 2;
    float2 uu = *(const float2*)(u + d);
    float2 ww = *(const float2*)(w + d);
    size_t base = ((size_t)b * TT + (size_t)c * LC) * DD + d;
    float P0 = 1.f, A0 = 0.f, B0 = 0.f;
    float P1 = 1.f, A1 = 0.f, B1 = 0.f;
#pragma unroll 4
    for (int t = 0; t < LC; t++) {
        size_t off = base + (size_t)t * DD;
        float2 kt = __half22float2(*(const __half2*)(k + off));
        float2 vt = __half22float2(*(const __half2*)(v + off));
        float mx0 = fmaxf(uu.x + kt.x, ww.x);
        float mx1 = fmaxf(uu.y + kt.y, ww.y);
        float e10 = __expf(-ww.x - mx0), e20 = __expf(uu.x + kt.x - mx0);
        float e11 = __expf(-ww.y - mx1), e21 = __expf(uu.y + kt.y - mx1);
        A0 = fmaf(e10, A0, e20 * vt.x);  B0 = fmaf(e10, B0, e20);  P0 *= e10;
        A1 = fmaf(e11, A1, e21 * vt.y);  B1 = fmaf(e11, B1, e21);  P1 *= e11;
    }
    size_t o = ((size_t)b * NC + c) * DD + d;
    *(float2*)(P + o)  = make_float2(P0, P1);
    *(float2*)(A + o)  = make_float2(A0, A1);
    *(float2*)(Bc + o) = make_float2(B0, B1);
}

__global__ void wkv_combine(const float* __restrict__ P, const float* __restrict__ A,
                            const float* __restrict__ Bc,
                            float* __restrict__ iA, float* __restrict__ iB) {
    int idx = blockIdx.x * blockDim.x + threadIdx.x;   // over BB*DD/2
    if (idx >= BB * DD / 2) return;
    int d = (idx % (DD / 2)) * 2;
    int b = idx / (DD / 2);
    float2 a = make_float2(0.f, 0.f), bd = make_float2(0.f, 0.f);
    for (int c = 0; c < NC; c++) {
        size_t o = ((size_t)b * NC + c) * DD + d;
        *(float2*)(iA + o) = a;
        *(float2*)(iB + o) = bd;
        float2 p  = *(const float2*)(P + o);
        float2 aa = *(const float2*)(A + o);
        float2 bb = *(const float2*)(Bc + o);
        a.x  = fmaf(p.x, a.x,  aa.x);  a.y  = fmaf(p.y, a.y,  aa.y);
        bd.x = fmaf(p.x, bd.x, bb.x);  bd.y = fmaf(p.y, bd.y, bb.y);
    }
}

__global__ void wkv_pass3(const __half* __restrict__ k, const __half* __restrict__ v,
                          const __half* __restrict__ r,
                          const float* __restrict__ u, const float* __restrict__ w,
                          const float* __restrict__ iA, const float* __restrict__ iB,
                          __half* __restrict__ out) {
    int idx = blockIdx.x * blockDim.x + threadIdx.x;   // over BB*NC*DD/2
    if (idx >= BB * NC * DD / 2) return;
    int d2 = idx % (DD / 2);
    int rest = idx / (DD / 2);
    int c = rest % NC;
    int b = rest / NC;
    int d = d2 * 2;
    float2 uu = *(const float2*)(u + d);
    float2 ww = *(const float2*)(w + d);
    size_t base = ((size_t)b * TT + (size_t)c * LC) * DD + d;
    size_t o = ((size_t)b * NC + c) * DD + d;
    float2 a  = *(const float2*)(iA + o);
    float2 bd = *(const float2*)(iB + o);
#pragma unroll 4
    for (int t = 0; t < LC; t++) {
        size_t off = base + (size_t)t * DD;
        float2 kt = __half22float2(*(const __half2*)(k + off));
        float2 vt = __half22float2(*(const __half2*)(v + off));
        float2 rt = __half22float2(*(const __half2*)(r + off));
        float mx0 = fmaxf(uu.x + kt.x, ww.x);
        float mx1 = fmaxf(uu.y + kt.y, ww.y);
        float e10 = __expf(-ww.x - mx0), e20 = __expf(uu.x + kt.x - mx0);
        float e11 = __expf(-ww.y - mx1), e21 = __expf(uu.y + kt.y - mx1);
        a.x  = fmaf(e10, a.x,  e20 * vt.x);  bd.x = fmaf(e10, bd.x, e20);
        a.y  = fmaf(e11, a.y,  e21 * vt.y);  bd.y = fmaf(e11, bd.y, e21);
        *(__half2*)(out + off) =
            __floats2half2_rn((a.x / bd.x) * rt.x, (a.y / bd.y) * rt.y);
    }
}

// ---------------- launch ---------------------------------------------------------
extern "C" void kernel_launch(void* const* d_in, const int* in_sizes, int n_in,
                              void* d_out, int out_size) {
    (void)in_sizes; (void)n_in; (void)out_size;
    const float* x   = (const float*)d_in[0];
    const float* Wk  = (const float*)d_in[1];
    const float* bk  = (const float*)d_in[2];
    const float* Wv  = (const float*)d_in[3];
    const float* bv  = (const float*)d_in[4];
    const float* Wr  = (const float*)d_in[5];
    const float* br  = (const float*)d_in[6];
    const float* Wo  = (const float*)d_in[7];
    const float* bo  = (const float*)d_in[8];
    const float* tmk = (const float*)d_in[9];
    const float* tmv = (const float*)d_in[10];
    const float* tmr = (const float*)d_in[11];
    const float* u   = (const float*)d_in[12];
    const float* w   = (const float*)d_in[13];
    float* out = (float*)d_out;

    __half *mixh, *Wh, *kvh, *rh, *wkvrh;
    float *P, *A, *Bc, *iA, *iB;
    cudaGetSymbolAddress((void**)&mixh,  g_mixh);
    cudaGetSymbolAddress((void**)&Wh,    g_Wh);
    cudaGetSymbolAddress((void**)&kvh,   g_kvh);
    cudaGetSymbolAddress((void**)&rh,    g_rh);
    cudaGetSymbolAddress((void**)&wkvrh, g_wkvrh);
    cudaGetSymbolAddress((void**)&P,     g_P);
    cudaGetSymbolAddress((void**)&A,     g_A);
    cudaGetSymbolAddress((void**)&Bc,    g_Bc);
    cudaGetSymbolAddress((void**)&iA,    g_iA);
    cudaGetSymbolAddress((void**)&iB,    g_iB);
    __half* kmix = mixh + 0 * (size_t)MM * DD;
    __half* kh = kvh;
    __half* vh = kvh + (size_t)MM * DD;

    static cudaStream_t s1 = nullptr;
    static cudaEvent_t ev0 = nullptr, ev1 = nullptr, evA = nullptr, evB = nullptr;
    if (s1 == nullptr) {
        cudaStreamCreateWithFlags(&s1, cudaStreamNonBlocking);
        cudaEventCreateWithFlags(&ev0, cudaEventDisableTiming);
        cudaEventCreateWithFlags(&ev1, cudaEventDisableTiming);
        cudaEventCreateWithFlags(&evA, cudaEventDisableTiming);
        cudaEventCreateWithFlags(&evB, cudaEventDisableTiming);
    }

    cudaFuncSetAttribute(gemm_fp16, cudaFuncAttributeMaxDynamicSharedMemorySize, GSMEM);

    // fork: wconv on s1, mix on main
    cudaEventRecord(ev0, 0);
    cudaStreamWaitEvent(s1, ev0, 0);
    dim3 wcGrid((DD * DD / 4 + 255) / 256, 4);
    wconv_kernel<<<wcGrid, 256, 0, s1>>>(Wk, Wv, Wr, Wo, Wh);
    cudaEventRecord(ev1, s1);

    int mixBlocks = (MM * DD / 4 + 255) / 256;
    mix_kernel<<<mixBlocks, 256>>>(x, tmk, tmv, tmr,
                                   kmix, mixh + (size_t)MM * DD, mixh + 2 * (size_t)MM * DD);
    cudaStreamWaitEvent(0, ev1, 0);

    // k/v GEMMs (z=0,1) -> fp16
    dim3 gkv(DD / BN, MM / BM, 2);
    gemm_fp16<<<gkv, 128, GSMEM>>>(mixh, Wh, bk, bv, nullptr, kvh);
    cudaEventRecord(evA, 0);

    // r GEMM on s1, after kv completes
    cudaStreamWaitEvent(s1, evA, 0);
    dim3 gr(DD / BN, MM / BM, 1);
    gemm_fp16<<<gr, 128, GSMEM, s1>>>(mixh + 2 * (size_t)MM * DD, Wh + 2 * (size_t)DD * DD,
                                      br, br, nullptr, rh);
    cudaEventRecord(evB, s1);

    // scan (pass1+combine) on main, concurrent with r GEMM
    const int SCAN2 = BB * NC * DD / 2;   // 262144
    wkv_pass1<<<SCAN2 / 256, 256>>>(kh, vh, u, w, P, A, Bc);
    wkv_combine<<<(BB * DD / 2 + 255) / 256, 256>>>(P, A, Bc, iA, iB);

    cudaStreamWaitEvent(0, evB, 0);
    wkv_pass3<<<SCAN2 / 256, 256>>>(kh, vh, rh, u, w, iA, iB, wkvrh);

    // final GEMM (fp32 out)
    gemm_fp16<<<gr, 128, GSMEM>>>(wkvrh, Wh + 3 * (size_t)DD * DD, bo, bo, out, nullptr);
}

// round 14
// speedup vs baseline: 1.0556x; 1.0011x over previous
#include <cuda_runtime.h>
#include <cuda_fp16.h>
#include <cstdint>

#define BB 4
#define TT 4096
#define DD 2048
#define MM (BB*TT)   // 16384
#define NC 64
#define LC (TT/NC)

// ---------------- scratch (device globals) ----------------------------------
__device__ __half g_mixh[3][(size_t)MM*DD];   // kmix, vmix, rmix (fp16)
__device__ __half g_Wh  [4][(size_t)DD*DD];   // Wk, Wv, Wr, Wo (fp16)
__device__ __half g_kvh [2][(size_t)MM*DD];   // k, v (fp16)
__device__ __half g_rh  [(size_t)MM*DD];      // r (fp16)
__device__ __half g_wkvrh[(size_t)MM*DD];     // (a/b)*r (fp16)
__device__ float g_P [(size_t)BB*NC*DD];
__device__ float g_A [(size_t)BB*NC*DD];
__device__ float g_Bc[(size_t)BB*NC*DD];
__device__ float g_iA[(size_t)BB*NC*DD];
__device__ float g_iB[(size_t)BB*NC*DD];

// ---------------- helpers -----------------------------------------------------
__device__ __forceinline__ void cp16(uint32_t dst, const void* src) {
    asm volatile("cp.async.cg.shared.global [%0], [%1], 16;" :: "r"(dst), "l"(src));
}
__device__ __forceinline__ void ldsm4(uint32_t& r0, uint32_t& r1, uint32_t& r2,
                                      uint32_t& r3, uint32_t addr) {
    asm volatile("ldmatrix.sync.aligned.m8n8.x4.shared.b16 {%0,%1,%2,%3}, [%4];"
                 : "=r"(r0), "=r"(r1), "=r"(r2), "=r"(r3) : "r"(addr));
}

// ---------------- weight convert (fp32 -> fp16) -------------------------------
__global__ void wconv_kernel(const float* __restrict__ w0, const float* __restrict__ w1,
                             const float* __restrict__ w2, const float* __restrict__ w3,
                             __half* __restrict__ out) {
    int i = blockIdx.x * blockDim.x + threadIdx.x;
    if (i >= DD * DD / 4) return;
    const float* src = (blockIdx.y == 0) ? w0 : (blockIdx.y == 1) ? w1 :
                       (blockIdx.y == 2) ? w2 : w3;
    float4 v = ((const float4*)src)[i];
    __half2 h01 = __floats2half2_rn(v.x, v.y);
    __half2 h23 = __floats2half2_rn(v.z, v.w);
    __half2* dst = (__half2*)(out + (size_t)blockIdx.y * DD * DD) + i * 2;
    dst[0] = h01; dst[1] = h23;
}

// ---------------- mix: time-shift + lerp (+silu for r) -> fp16 ----------------
__global__ void mix_kernel(const float* __restrict__ x,
                           const float* __restrict__ tmk,
                           const float* __restrict__ tmv,
                           const float* __restrict__ tmr,
                           __half* __restrict__ km,
                           __half* __restrict__ vm,
                           __half* __restrict__ rm) {
    int i4 = blockIdx.x * blockDim.x + threadIdx.x;
    if (i4 >= MM * DD / 4) return;
    size_t i = (size_t)i4 * 4;
    int m = (int)(i / DD);
    int d = (int)(i % DD);
    int t = m % TT;
    float4 xv = *(const float4*)(x + i);
    float4 xs = (t > 0) ? *(const float4*)(x + i - DD) : make_float4(0.f, 0.f, 0.f, 0.f);
    float4 mk = *(const float4*)(tmk + d);
    float4 mv = *(const float4*)(tmv + d);
    float4 mr = *(const float4*)(tmr + d);

    __half2 h01, h23;
    h01 = __floats2half2_rn(xv.x * mk.x + xs.x * (1.f - mk.x),
                            xv.y * mk.y + xs.y * (1.f - mk.y));
    h23 = __floats2half2_rn(xv.z * mk.z + xs.z * (1.f - mk.z),
                            xv.w * mk.w + xs.w * (1.f - mk.w));
    ((__half2*)(km + i))[0] = h01; ((__half2*)(km + i))[1] = h23;

    h01 = __floats2half2_rn(xv.x * mv.x + xs.x * (1.f - mv.x),
                            xv.y * mv.y + xs.y * (1.f - mv.y));
    h23 = __floats2half2_rn(xv.z * mv.z + xs.z * (1.f - mv.z),
                            xv.w * mv.w + xs.w * (1.f - mv.w));
    ((__half2*)(vm + i))[0] = h01; ((__half2*)(vm + i))[1] = h23;

    float s0, s1, s2, s3;
    s0 = xv.x * mr.x + xs.x * (1.f - mr.x); s0 = s0 / (1.f + __expf(-s0));
    s1 = xv.y * mr.y + xs.y * (1.f - mr.y); s1 = s1 / (1.f + __expf(-s1));
    s2 = xv.z * mr.z + xs.z * (1.f - mr.z); s2 = s2 / (1.f + __expf(-s2));
    s3 = xv.w * mr.w + xs.w * (1.f - mr.w); s3 = s3 / (1.f + __expf(-s3));
    ((__half2*)(rm + i))[0] = __floats2half2_rn(s0, s1);
    ((__half2*)(rm + i))[1] = __floats2half2_rn(s2, s3);
}

// ---------------- fp16 GEMM: 128 threads, 2x2 warps of 64x64, 2 CTAs/SM ---------
constexpr int BM = 128, BN = 128, BKH = 64, STAGES = 3;
constexpr int A_STAGE_B = BM * 128;
constexpr int B_STAGE_B = BN * 128;
constexpr int STAGE_B   = A_STAGE_B + B_STAGE_B;  // 32768
constexpr int GSMEM     = STAGES * STAGE_B;       // 98304

__global__ __launch_bounds__(128, 2)
void gemm_fp16(const __half* __restrict__ Abase, const __half* __restrict__ Wbase,
               const float* __restrict__ b0p, const float* __restrict__ b1p,
               float* __restrict__ Cbase, __half* __restrict__ Chbase) {
    extern __shared__ char smem[];
    uint32_t sb = (uint32_t)__cvta_generic_to_shared(smem);
    const int K = DD, N = DD;

    int z = blockIdx.z;
    const __half* A = Abase + (size_t)z * MM * DD;
    const __half* W = Wbase + (size_t)z * DD * DD;
    const float* bias = (z == 0) ? b0p : b1p;

    int tid  = threadIdx.x;
    int m0   = blockIdx.y * BM;
    int n0   = blockIdx.x * BN;
    int warp = tid >> 5, lane = tid & 31;
    int wm = warp >> 1, wn = warp & 1;
    int g  = lane >> 2, tg = lane & 3;

    float acc[4][8][4];
#pragma unroll
    for (int a = 0; a < 4; a++)
#pragma unroll
        for (int b = 0; b < 8; b++)
#pragma unroll
            for (int c = 0; c < 4; c++) acc[a][b][c] = 0.f;

    auto load_stage = [&](int s, int ko) {
        uint32_t base = sb + s * STAGE_B;
#pragma unroll
        for (int i = 0; i < 8; i++) {
            int c  = tid + i * 128;
            int r  = c >> 3;
            int gp = c & 7;
            int pg = gp ^ (r & 7);
            cp16(base + (uint32_t)(r * 128 + pg * 16),
                 A + (size_t)(m0 + r) * K + ko + gp * 8);
        }
#pragma unroll
        for (int i = 0; i < 8; i++) {
            int c  = tid + i * 128;
            int r  = c >> 3;
            int gp = c & 7;
            int pg = gp ^ (r & 7);
            cp16(base + (uint32_t)(A_STAGE_B + r * 128 + pg * 16),
                 W + (size_t)(n0 + r) * K + ko + gp * 8);
        }
        asm volatile("cp.async.commit_group;");
    };

    load_stage(0, 0);
    load_stage(1, BKH);

    int a_row16 = lane & 15;
    int a_khalf = lane >> 4;
    int b_row   = ((lane >> 4) << 3) + (lane & 7);
    int b_khalf = (lane >> 3) & 1;

    const int KT = K / BKH;   // 32
    for (int kt = 0; kt < KT; kt++) {
        if (kt < KT - 1) asm volatile("cp.async.wait_group 1;");
        else             asm volatile("cp.async.wait_group 0;");
        __syncthreads();
        if (kt + 2 < KT) load_stage((kt + 2) % 3, (kt + 2) * BKH);

        uint32_t sa  = sb + (kt % 3) * STAGE_B;
        uint32_t sbm = sa + A_STAGE_B;
#pragma unroll
        for (int ks = 0; ks < 4; ks++) {
            int kg = ks * 2;
            uint32_t af[4][4], bf[8][2];
#pragma unroll
            for (int mt = 0; mt < 4; mt++) {
                int mr = wm * 64 + mt * 16 + a_row16;
                int gp = (kg + a_khalf) ^ (mr & 7);
                ldsm4(af[mt][0], af[mt][1], af[mt][2], af[mt][3],
                      sa + (uint32_t)(mr * 128 + gp * 16));
            }
#pragma unroll
            for (int p = 0; p < 4; p++) {
                int nr = wn * 64 + p * 16 + b_row;
                int gp = (kg + b_khalf) ^ (nr & 7);
                ldsm4(bf[2 * p][0], bf[2 * p][1], bf[2 * p + 1][0], bf[2 * p + 1][1],
                      sbm + (uint32_t)(nr * 128 + gp * 16));
            }
#pragma unroll
            for (int mt = 0; mt < 4; mt++)
#pragma unroll
                for (int nt = 0; nt < 8; nt++) {
                    asm volatile(
                        "mma.sync.aligned.m16n8k16.row.col.f32.f16.f16.f32 "
                        "{%0,%1,%2,%3}, {%4,%5,%6,%7}, {%8,%9}, {%0,%1,%2,%3};"
                        : "+f"(acc[mt][nt][0]), "+f"(acc[mt][nt][1]),
                          "+f"(acc[mt][nt][2]), "+f"(acc[mt][nt][3])
                        : "r"(af[mt][0]), "r"(af[mt][1]), "r"(af[mt][2]), "r"(af[mt][3]),
                          "r"(bf[nt][0]), "r"(bf[nt][1]));
                }
        }
    }

    if (Chbase != nullptr) {
        __half* Ch = Chbase + (size_t)z * MM * DD;
#pragma unroll
        for (int mt = 0; mt < 4; mt++) {
#pragma unroll
            for (int nt = 0; nt < 8; nt++) {
                int m = m0 + wm * 64 + mt * 16 + g;
                int n = n0 + wn * 64 + nt * 8 + tg * 2;
                float b0 = bias[n], b1 = bias[n + 1];
                *(__half2*)(Ch + (size_t)m * N + n) =
                    __floats2half2_rn(acc[mt][nt][0] + b0, acc[mt][nt][1] + b1);
                *(__half2*)(Ch + (size_t)(m + 8) * N + n) =
                    __floats2half2_rn(acc[mt][nt][2] + b0, acc[mt][nt][3] + b1);
            }
        }
    } else {
        float* C = Cbase;
#pragma unroll
        for (int mt = 0; mt < 4; mt++) {
#pragma unroll
            for (int nt = 0; nt < 8; nt++) {
                int m = m0 + wm * 64 + mt * 16 + g;
                int n = n0 + wn * 64 + nt * 8 + tg * 2;
                float b0 = bias[n], b1 = bias[n + 1];
                float2 v0 = make_float2(acc[mt][nt][0] + b0, acc[mt][nt][1] + b1);
                float2 v1 = make_float2(acc[mt][nt][2] + b0, acc[mt][nt][3] + b1);
                *(float2*)(C + (size_t)m * N + n)       = v0;
                *(float2*)(C + (size_t)(m + 8) * N + n) = v1;
            }
        }
    }
}

// ---------------- chunked WKV scan: 2 channels/thread, small co-residable blocks
__global__ __launch_bounds__(64)
void wkv_pass1(const __half* __restrict__ k, const __half* __restrict__ v,
               const float* __restrict__ u, const float* __restrict__ w,
               float* __restrict__ P, float* __restrict__ A,
               float* __restrict__ Bc) {
    int idx = blockIdx.x * blockDim.x + threadIdx.x;   // over BB*NC*DD/2
    if (idx >= BB * NC * DD / 2) return;
    int d2 = idx % (DD / 2);
    int rest = idx / (DD / 2);
    int c = rest % NC;
    int b = rest / NC;
    int d = d2 * 2;
    float2 uu = *(const float2*)(u + d);
    float2 ww = *(const float2*)(w + d);
    size_t base = ((size_t)b * TT + (size_t)c * LC) * DD + d;
    float P0 = 1.f, A0 = 0.f, B0 = 0.f;
    float P1 = 1.f, A1 = 0.f, B1 = 0.f;
#pragma unroll 4
    for (int t = 0; t < LC; t++) {
        size_t off = base + (size_t)t * DD;
        float2 kt = __half22float2(*(const __half2*)(k + off));
        float2 vt = __half22float2(*(const __half2*)(v + off));
        float mx0 = fmaxf(uu.x + kt.x, ww.x);
        float mx1 = fmaxf(uu.y + kt.y, ww.y);
        float e10 = __expf(-ww.x - mx0), e20 = __expf(uu.x + kt.x - mx0);
        float e11 = __expf(-ww.y - mx1), e21 = __expf(uu.y + kt.y - mx1);
        A0 = fmaf(e10, A0, e20 * vt.x);  B0 = fmaf(e10, B0, e20);  P0 *= e10;
        A1 = fmaf(e11, A1, e21 * vt.y);  B1 = fmaf(e11, B1, e21);  P1 *= e11;
    }
    size_t o = ((size_t)b * NC + c) * DD + d;
    *(float2*)(P + o)  = make_float2(P0, P1);
    *(float2*)(A + o)  = make_float2(A0, A1);
    *(float2*)(Bc + o) = make_float2(B0, B1);
}

__global__ __launch_bounds__(64)
void wkv_combine(const float* __restrict__ P, const float* __restrict__ A,
                 const float* __restrict__ Bc,
                 float* __restrict__ iA, float* __restrict__ iB) {
    int idx = blockIdx.x * blockDim.x + threadIdx.x;   // over BB*DD/2
    if (idx >= BB * DD / 2) return;
    int d = (idx % (DD / 2)) * 2;
    int b = idx / (DD / 2);
    float2 a = make_float2(0.f, 0.f), bd = make_float2(0.f, 0.f);
    for (int c = 0; c < NC; c++) {
        size_t o = ((size_t)b * NC + c) * DD + d;
        *(float2*)(iA + o) = a;
        *(float2*)(iB + o) = bd;
        float2 p  = *(const float2*)(P + o);
        float2 aa = *(const float2*)(A + o);
        float2 bb = *(const float2*)(Bc + o);
        a.x  = fmaf(p.x, a.x,  aa.x);  a.y  = fmaf(p.y, a.y,  aa.y);
        bd.x = fmaf(p.x, bd.x, bb.x);  bd.y = fmaf(p.y, bd.y, bb.y);
    }
}

__global__ void wkv_pass3(const __half* __restrict__ k, const __half* __restrict__ v,
                          const __half* __restrict__ r,
                          const float* __restrict__ u, const float* __restrict__ w,
                          const float* __restrict__ iA, const float* __restrict__ iB,
                          __half* __restrict__ out) {
    int idx = blockIdx.x * blockDim.x + threadIdx.x;   // over BB*NC*DD/2
    if (idx >= BB * NC * DD / 2) return;
    int d2 = idx % (DD / 2);
    int rest = idx / (DD / 2);
    int c = rest % NC;
    int b = rest / NC;
    int d = d2 * 2;
    float2 uu = *(const float2*)(u + d);
    float2 ww = *(const float2*)(w + d);
    size_t base = ((size_t)b * TT + (size_t)c * LC) * DD + d;
    size_t o = ((size_t)b * NC + c) * DD + d;
    float2 a  = *(const float2*)(iA + o);
    float2 bd = *(const float2*)(iB + o);
#pragma unroll 4
    for (int t = 0; t < LC; t++) {
        size_t off = base + (size_t)t * DD;
        float2 kt = __half22float2(*(const __half2*)(k + off));
        float2 vt = __half22float2(*(const __half2*)(v + off));
        float2 rt = __half22float2(*(const __half2*)(r + off));
        float mx0 = fmaxf(uu.x + kt.x, ww.x);
        float mx1 = fmaxf(uu.y + kt.y, ww.y);
        float e10 = __expf(-ww.x - mx0), e20 = __expf(uu.x + kt.x - mx0);
        float e11 = __expf(-ww.y - mx1), e21 = __expf(uu.y + kt.y - mx1);
        a.x  = fmaf(e10, a.x,  e20 * vt.x);  bd.x = fmaf(e10, bd.x, e20);
        a.y  = fmaf(e11, a.y,  e21 * vt.y);  bd.y = fmaf(e11, bd.y, e21);
        *(__half2*)(out + off) =
            __floats2half2_rn((a.x / bd.x) * rt.x, (a.y / bd.y) * rt.y);
    }
}

// ---------------- launch ---------------------------------------------------------
extern "C" void kernel_launch(void* const* d_in, const int* in_sizes, int n_in,
                              void* d_out, int out_size) {
    (void)in_sizes; (void)n_in; (void)out_size;
    const float* x   = (const float*)d_in[0];
    const float* Wk  = (const float*)d_in[1];
    const float* bk  = (const float*)d_in[2];
    const float* Wv  = (const float*)d_in[3];
    const float* bv  = (const float*)d_in[4];
    const float* Wr  = (const float*)d_in[5];
    const float* br  = (const float*)d_in[6];
    const float* Wo  = (const float*)d_in[7];
    const float* bo  = (const float*)d_in[8];
    const float* tmk = (const float*)d_in[9];
    const float* tmv = (const float*)d_in[10];
    const float* tmr = (const float*)d_in[11];
    const float* u   = (const float*)d_in[12];
    const float* w   = (const float*)d_in[13];
    float* out = (float*)d_out;

    __half *mixh, *Wh, *kvh, *rh, *wkvrh;
    float *P, *A, *Bc, *iA, *iB;
    cudaGetSymbolAddress((void**)&mixh,  g_mixh);
    cudaGetSymbolAddress((void**)&Wh,    g_Wh);
    cudaGetSymbolAddress((void**)&kvh,   g_kvh);
    cudaGetSymbolAddress((void**)&rh,    g_rh);
    cudaGetSymbolAddress((void**)&wkvrh, g_wkvrh);
    cudaGetSymbolAddress((void**)&P,     g_P);
    cudaGetSymbolAddress((void**)&A,     g_A);
    cudaGetSymbolAddress((void**)&Bc,    g_Bc);
    cudaGetSymbolAddress((void**)&iA,    g_iA);
    cudaGetSymbolAddress((void**)&iB,    g_iB);
    __half* kmix = mixh + 0 * (size_t)MM * DD;
    __half* kh = kvh;
    __half* vh = kvh + (size_t)MM * DD;

    static cudaStream_t s1 = nullptr;
    static cudaEvent_t ev0 = nullptr, ev1 = nullptr, evA = nullptr, evB = nullptr;
    if (s1 == nullptr) {
        cudaStreamCreateWithFlags(&s1, cudaStreamNonBlocking);
        cudaEventCreateWithFlags(&ev0, cudaEventDisableTiming);
        cudaEventCreateWithFlags(&ev1, cudaEventDisableTiming);
        cudaEventCreateWithFlags(&evA, cudaEventDisableTiming);
        cudaEventCreateWithFlags(&evB, cudaEventDisableTiming);
    }

    cudaFuncSetAttribute(gemm_fp16, cudaFuncAttributeMaxDynamicSharedMemorySize, GSMEM);

    // fork: wconv on s1, mix on main
    cudaEventRecord(ev0, 0);
    cudaStreamWaitEvent(s1, ev0, 0);
    dim3 wcGrid((DD * DD / 4 + 255) / 256, 4);
    wconv_kernel<<<wcGrid, 256, 0, s1>>>(Wk, Wv, Wr, Wo, Wh);
    cudaEventRecord(ev1, s1);

    int mixBlocks = (MM * DD / 4 + 255) / 256;
    mix_kernel<<<mixBlocks, 256>>>(x, tmk, tmv, tmr,
                                   kmix, mixh + (size_t)MM * DD, mixh + 2 * (size_t)MM * DD);
    cudaStreamWaitEvent(0, ev1, 0);

    // k/v GEMMs (z=0,1) -> fp16
    dim3 gkv(DD / BN, MM / BM, 2);
    gemm_fp16<<<gkv, 128, GSMEM>>>(mixh, Wh, bk, bv, nullptr, kvh);
    cudaEventRecord(evA, 0);

    // r GEMM on s1, after kv completes
    cudaStreamWaitEvent(s1, evA, 0);
    dim3 gr(DD / BN, MM / BM, 1);
    gemm_fp16<<<gr, 128, GSMEM, s1>>>(mixh + 2 * (size_t)MM * DD, Wh + 2 * (size_t)DD * DD,
                                      br, br, nullptr, rh);
    cudaEventRecord(evB, s1);

    // scan (pass1+combine) on main: 64-thread blocks co-reside with the r GEMM
    const int SCAN2 = BB * NC * DD / 2;   // 262144
    wkv_pass1<<<SCAN2 / 64, 64>>>(kh, vh, u, w, P, A, Bc);
    wkv_combine<<<(BB * DD / 2 + 63) / 64, 64>>>(P, A, Bc, iA, iB);

    cudaStreamWaitEvent(0, evB, 0);
    wkv_pass3<<<SCAN2 / 256, 256>>>(kh, vh, rh, u, w, iA, iB, wkvrh);

    // final GEMM (fp32 out)
    gemm_fp16<<<gr, 128, GSMEM>>>(wkvrh, Wh + 3 * (size_t)DD * DD, bo, bo, out, nullptr);
}